// round 9
// baseline (speedup 1.0000x reference)
#include <cuda_runtime.h>

// ---------------------------------------------------------------------------
// MambaSSM: B=2, L=384, d_inner=384, d_state=384, dt_rank=384, d_conv=4
//
//   GEMM1 (fused): dt = softplus(x @ dt_w^T + dt_b)   -> g_DT   [768x384]
//                  x_dbl = x @ B_w^T                  -> g_XDBL [768x384]
//   K3:            u = silu(causal_conv(x)+cb);
//                  g_SC[b][d][l] = (dt, dt, dt*u, dt*u)  (f32x2-ready pairs)
//                  g_UD[b][d][l] = u*D[d]
//   GEMM2 (fused): Bm = x_dbl @ B_w^T -> g_BM ; Cm = x_dbl @ C_w^T -> g_CM
//   SCAN v9 = v5 structure + packed f32x2 math:
//     CTA = 2 channels x 192 float2-lanes = 384 threads, grid 384.
//     inner loop: mul2/fma2 on (hx,hy) pairs, 2 MUFU, deferred 2-level shfl;
//     unroll-2 C ping-pong; sc staged in smem double buffer.
// ---------------------------------------------------------------------------

#define LOG2E 1.4426950408889634f

__device__ float  g_DT  [768 * 384];
__device__ float  g_XDBL[768 * 384];
__device__ float  g_BM  [768 * 384];
__device__ float  g_CM  [768 * 384];
__device__ float4 g_SC  [768 * 384];   // (dt, dt, dt*u, dt*u)
__device__ float  g_UD  [768 * 384];   // u * D[d]

__device__ __forceinline__ float ex2f(float x) {
    float y;
    asm("ex2.approx.ftz.f32 %0, %1;" : "=f"(y) : "f"(x));
    return y;
}

#define MUL2(out, a, b) \
    asm("mul.rn.f32x2 %0, %1, %2;" : "=l"(out) : "l"(a), "l"(b))
#define FMA2(out, a, b, c) \
    asm("fma.rn.f32x2 %0, %1, %2, %3;" : "=l"(out) : "l"(a), "l"(b), "l"(c))
#define PACK2(v, lo, hi) \
    asm("mov.b64 %0, {%1, %2};" : "=l"(v) : "f"(lo), "f"(hi))
#define UNPACK2(lo, hi, v) \
    asm("mov.b64 {%0, %1}, %2;" : "=f"(lo), "=f"(hi) : "l"(v))

// ---------------------------------------------------------------------------
// Dual-output tiled SGEMM (proven v5): 64x64 tiles, grid (12,12).
// ---------------------------------------------------------------------------
__global__ __launch_bounds__(256) void gemm_dual(
    const float* __restrict__ A_ext,
    const float* __restrict__ Wa,
    const float* __restrict__ Wb,
    const float* __restrict__ bias,
    int phase)
{
    __shared__ float As[16][64];
    __shared__ float Bs[16][64];

    const float* A  = (phase == 0) ? A_ext : g_XDBL;
    float*       Ca = (phase == 0) ? g_DT  : g_BM;
    float*       Cb = (phase == 0) ? g_XDBL: g_CM;

    const int tid = threadIdx.x;
    const int m0  = blockIdx.x * 64;
    const int bn  = blockIdx.y;            // 0..11
    const bool second = (bn >= 6);
    const float* W  = second ? Wb : Wa;
    float*       Cc = second ? Cb : Ca;
    const bool doAct = (phase == 0) && !second;
    const int n0 = (second ? bn - 6 : bn) * 64;

    const int loadRow = tid >> 2;          // 0..63
    const int loadCol = (tid & 3) << 2;    // 0,4,8,12
    const float* Ap = A + (m0 + loadRow) * 384 + loadCol;
    const float* Wp = W + (n0 + loadRow) * 384 + loadCol;

    float4 aR = *(const float4*)Ap;
    float4 wR = *(const float4*)Wp;

    float acc[4][4];
#pragma unroll
    for (int i = 0; i < 4; i++)
#pragma unroll
        for (int j = 0; j < 4; j++) acc[i][j] = 0.f;

    const int tx = tid & 15;
    const int ty = tid >> 4;

    for (int kt = 0; kt < 24; ++kt) {
        As[loadCol + 0][loadRow] = aR.x;
        As[loadCol + 1][loadRow] = aR.y;
        As[loadCol + 2][loadRow] = aR.z;
        As[loadCol + 3][loadRow] = aR.w;
        Bs[loadCol + 0][loadRow] = wR.x;
        Bs[loadCol + 1][loadRow] = wR.y;
        Bs[loadCol + 2][loadRow] = wR.z;
        Bs[loadCol + 3][loadRow] = wR.w;
        __syncthreads();

        if (kt < 23) {
            aR = *(const float4*)(Ap + (kt + 1) * 16);
            wR = *(const float4*)(Wp + (kt + 1) * 16);
        }

#pragma unroll
        for (int k = 0; k < 16; ++k) {
            float4 av = *(const float4*)&As[k][ty << 2];
            float4 bv = *(const float4*)&Bs[k][tx << 2];
            float a[4] = {av.x, av.y, av.z, av.w};
            float b[4] = {bv.x, bv.y, bv.z, bv.w};
#pragma unroll
            for (int i = 0; i < 4; i++)
#pragma unroll
                for (int j = 0; j < 4; j++)
                    acc[i][j] = fmaf(a[i], b[j], acc[i][j]);
        }
        __syncthreads();
    }

#pragma unroll
    for (int i = 0; i < 4; i++) {
        const int m = m0 + (ty << 2) + i;
#pragma unroll
        for (int j = 0; j < 4; j++) {
            const int n = n0 + (tx << 2) + j;
            float v = acc[i][j];
            if (doAct) {
                v += bias[n];
                v = fmaxf(v, 0.f) + log1pf(expf(-fabsf(v)));
            }
            Cc[m * 384 + n] = v;
        }
    }
}

// ---------------------------------------------------------------------------
// K3: causal depthwise conv(4) + silu; pack (dt,dt,dtu,dtu) + uD stream.
// ---------------------------------------------------------------------------
__global__ __launch_bounds__(384) void conv_sc_kernel(
    const float* __restrict__ x,
    const float* __restrict__ convw,
    const float* __restrict__ convb,
    const float* __restrict__ Dvec)
{
    const int d  = threadIdx.x;
    const int b  = blockIdx.y;
    const int l0 = blockIdx.x * 16;

    const float c0 = convw[d * 4 + 0];
    const float c1 = convw[d * 4 + 1];
    const float c2 = convw[d * 4 + 2];
    const float c3 = convw[d * 4 + 3];
    const float cb = convb[d];
    const float Dd = Dvec[d];

    const float* xb  = x    + b * 384 * 384 + d;
    const float* dtp = g_DT + b * 384 * 384 + d;
    float4* scp = g_SC + (b * 384 + d) * 384;
    float*  udp = g_UD + (b * 384 + d) * 384;

    float w0 = (l0 - 3 >= 0) ? xb[(l0 - 3) * 384] : 0.f;
    float w1 = (l0 - 2 >= 0) ? xb[(l0 - 2) * 384] : 0.f;
    float w2 = (l0 - 1 >= 0) ? xb[(l0 - 1) * 384] : 0.f;

    for (int i = 0; i < 16; ++i) {
        const int l = l0 + i;
        const float w3 = xb[l * 384];
        float v = fmaf(w0, c0, fmaf(w1, c1, fmaf(w2, c2, fmaf(w3, c3, cb))));
        const float u  = v / (1.f + expf(-v));     // silu
        const float dt = dtp[l * 384];
        const float du = dt * u;
        scp[l] = make_float4(dt, dt, du, du);
        udp[l] = u * Dd;
        w0 = w1; w1 = w2; w2 = w3;
    }
}

// ---------------------------------------------------------------------------
// SCAN v9: grid 384, block 384. CTA = 2 channels of one batch.
// ---------------------------------------------------------------------------
#define TL 48   // l-tile between smem reductions (384/48 = 8 tiles)

__global__ __launch_bounds__(384) void scan_kernel(
    const float* __restrict__ A_log,
    float* __restrict__ out)
{
    __shared__ float  part[2][TL][49];     // [ch][l_in_tile][48 partials + pad]
    __shared__ float4 scbuf[2][2][TL];     // [buf][ch][l_in_tile]

    const int tid  = threadIdx.x;
    const int lane = tid & 31;
    const int ch   = tid >= 192;
    const int s2   = tid - ch * 192;        // float2-state index 0..191
    const int wid6 = (tid >> 5) - ch * 6;   // warp index within channel 0..5

    const int pid   = blockIdx.x;           // 0..383
    const int b     = pid / 192;
    const int dbase = (pid - b * 192) * 2;
    const int d     = dbase + ch;

    // Per-thread invariants (packed)
    const float2 a = ((const float2*)(A_log + d * 384))[s2];
    const float A2x = -ex2f(a.x * LOG2E) * LOG2E;
    const float A2y = -ex2f(a.y * LOG2E) * LOG2E;
    unsigned long long A2p;  PACK2(A2p, A2x, A2y);
    const float2 bm = ((const float2*)(g_BM + (b * 384 + d) * 384))[s2];
    unsigned long long bm2;  PACK2(bm2, bm.x, bm.y);
    unsigned long long h2 = 0ull;          // (hx, hy) = (0, 0)

    const float4* scp0 = g_SC + (b * 384 + dbase) * 384;   // channel-0 stream
    const float*  udp0 = g_UD + (b * 384 + dbase) * 384;
    const unsigned long long* Cb2 =
        (const unsigned long long*)(g_CM + b * 147456) + s2;

    // Preload tile 0 sc (threads 0..95: c = tid/48, li = tid%48)
    if (tid < 96) {
        const int c = tid / TL, li = tid - c * TL;
        scbuf[0][c][li] = __ldg(scp0 + c * 384 + li);
    }
    unsigned long long C0 = __ldg(Cb2);
    unsigned long long C1 = __ldg(Cb2 + 192);
    __syncthreads();

    float accP = 0.f;

#define STEP(IDX, CREG)                                                     \
    {                                                                       \
        const ulonglong2 sc = *(const ulonglong2*)&scbuf[buf][ch][IDX];     \
        const unsigned long long Cv = CREG;                                 \
        const int lpf = lbase + (IDX) + 2;                                  \
        CREG = __ldg(Cb2 + (lpf < 384 ? lpf : 383) * 192);                  \
        unsigned long long t, g, p, e2v;                                    \
        MUL2(t, sc.x, A2p);                                                 \
        float tlo, thi;  UNPACK2(tlo, thi, t);                              \
        PACK2(e2v, ex2f(tlo), ex2f(thi));                                   \
        MUL2(g, sc.y, bm2);                                                 \
        FMA2(h2, e2v, h2, g);                                               \
        MUL2(p, h2, Cv);                                                    \
        float plo, phi;  UNPACK2(plo, phi, p);                              \
        const float acc = plo + phi;                                        \
        if ((IDX) > 0) {                                                    \
            accP += __shfl_xor_sync(0xffffffffu, accP, 16);                 \
            accP += __shfl_xor_sync(0xffffffffu, accP, 8);                  \
            if (lane < 8) part[ch][(IDX) - 1][wid6 * 8 + lane] = accP;      \
        }                                                                   \
        accP = acc;                                                         \
    }

    for (int tile = 0; tile < 8; ++tile) {
        const int lbase = tile * TL;
        const int buf   = tile & 1;

#pragma unroll 6
        for (int i = 0; i < TL; i += 2) {
            STEP(i, C0)
            STEP(i + 1, C1)
        }
        // flush last iteration of the tile
        accP += __shfl_xor_sync(0xffffffffu, accP, 16);
        accP += __shfl_xor_sync(0xffffffffu, accP, 8);
        if (lane < 8) part[ch][TL - 1][wid6 * 8 + lane] = accP;
        __syncthreads();

        // Reduce + write out (tid<96); load next tile's sc (tid 96..191)
        if (tid < 96) {
            const int c  = tid / TL;
            const int li = tid - c * TL;
            const float* p = part[c][li];
            float t0 = 0.f, t1 = 0.f, t2 = 0.f, t3 = 0.f;
#pragma unroll
            for (int j = 0; j < 48; j += 4) {
                t0 += p[j]; t1 += p[j + 1]; t2 += p[j + 2]; t3 += p[j + 3];
            }
            const int l = lbase + li;
            float y = (t0 + t1) + (t2 + t3);
            y += __ldg(udp0 + c * 384 + l);        // u*D term
            out[(size_t)b * 147456 + (size_t)l * 384 + dbase + c] = y;
        } else if (tid < 192 && tile < 7) {
            const int t2i = tid - 96;
            const int c = t2i / TL, li = t2i - c * TL;
            scbuf[buf ^ 1][c][li] = __ldg(scp0 + c * 384 + lbase + TL + li);
        }
        __syncthreads();
    }
#undef STEP
}

// ---------------------------------------------------------------------------
extern "C" void kernel_launch(void* const* d_in, const int* in_sizes, int n_in,
                              void* d_out, int out_size)
{
    const float* x      = (const float*)d_in[0];
    const float* A_log  = (const float*)d_in[1];
    const float* Dvec   = (const float*)d_in[2];
    const float* dt_w   = (const float*)d_in[3];
    const float* dt_b   = (const float*)d_in[4];
    const float* B_w    = (const float*)d_in[5];
    const float* C_w    = (const float*)d_in[6];
    const float* conv_w = (const float*)d_in[7];
    const float* conv_b = (const float*)d_in[8];
    float* out = (float*)d_out;

    gemm_dual<<<dim3(12, 12), 256>>>(x, dt_w, B_w, dt_b, 0);
    conv_sc_kernel<<<dim3(24, 2), 384>>>(x, conv_w, conv_b, Dvec);
    gemm_dual<<<dim3(12, 12), 256>>>(x, B_w, C_w, nullptr, 1);
    scan_kernel<<<384, 384>>>(A_log, out);
}